// round 13
// baseline (speedup 1.0000x reference)
#include <cuda_runtime.h>
#include <cstddef>

// Problem constants (fixed by the dataset problem)
#define CC 32
#define HH 128
#define WW 512
#define PAD 40
#define DD (PAD + 1)

// out[c,d,h,w] = in1[c,h,w] * (w >= d ? in2[c,h,w-d] : 0)
//
// One CTA per (c,h) row (4096 CTAs, 128 threads). in2 row staged once into
// shared memory with a PAD-float zero apron. Thread t owns the aligned float4
// at w = 4t; the shifted in2 window lives in 4 rotating registers.
//
// d-loop unrolled by 2 (R10 structure — best measured): plane d and d+1 are
// stored from one window state; the window then advances by 2 via two
// independent SHFL.UPs (prev-lane b2, b3), halving the per-plane shuffle
// dependency chain. Only lane 0 touches shared in the loop.
//
// Stores use DEFAULT caching (no hint): .cs measured 53.3us, .wt regressed
// to 59.5us; this is the last untested store-policy cell on the fast
// structure.
__global__ __launch_bounds__(128) void corr1d_row_kernel(
    const float* __restrict__ in1,
    const float* __restrict__ in2,
    float* __restrict__ out)
{
    __shared__ float s2[PAD + WW];   // 552 floats; [0,PAD) is the zero apron

    const int row  = blockIdx.x;     // (c,h) in [0, C*H)
    const int t    = threadIdx.x;    // 0..127
    const int lane = t & 31;
    const int c    = row / HH;
    const int h    = row % HH;

    // Stage rows. PAD*4 = 160 bytes, 16B-aligned, so float4 stores into
    // s2+PAD are legal.
    const float4 a = reinterpret_cast<const float4*>(in1 + (size_t)row * WW)[t];
    if (t < PAD) s2[t] = 0.0f;
    reinterpret_cast<float4*>(s2 + PAD)[t] =
        reinterpret_cast<const float4*>(in2 + (size_t)row * WW)[t];
    __syncthreads();

    // Output base for d=0 plane of this (c,h) row; planes are HH*WW apart.
    float4* po = reinterpret_cast<float4*>(
        out + ((size_t)(c * DD) * HH + h) * WW) + t;
    const size_t plane_stride_v4 = (size_t)HH * WW / 4;   // 16384 float4s

    // d=0 window: one aligned LDS.128.
    float4 b = reinterpret_cast<const float4*>(s2 + PAD)[t];
    float b0 = b.x, b1 = b.y, b2 = b.z, b3 = b.w;

    const int base = PAD + 4 * t;    // s2 index of b0 at d=0

    #pragma unroll
    for (int d = 0; d < PAD; d += 2) {
        // Fetch both carries up front (independent shuffles, issued in
        // parallel; latency covered by the two stores below).
        float carry0 = __shfl_up_sync(0xffffffffu, b2, 1);  // W[base-d-2]
        float carry1 = __shfl_up_sync(0xffffffffu, b3, 1);  // W[base-d-1]
        if (lane == 0) {
            carry0 = s2[base - d - 2];   // warp-boundary fill (apron-safe)
            carry1 = s2[base - d - 1];
        }

        // Plane d: window (b0, b1, b2, b3).
        float4 r0;
        r0.x = a.x * b0;
        r0.y = a.y * b1;
        r0.z = a.z * b2;
        r0.w = a.w * b3;
        po[(size_t)d * plane_stride_v4] = r0;          // default-cached store

        // Plane d+1: window (carry1, b0, b1, b2).
        float4 r1;
        r1.x = a.x * carry1;
        r1.y = a.y * b0;
        r1.z = a.z * b1;
        r1.w = a.w * b2;
        po[(size_t)(d + 1) * plane_stride_v4] = r1;    // default-cached store

        // Advance window by 2 disparities.
        b3 = b1;
        b2 = b0;
        b1 = carry1;
        b0 = carry0;
    }

    // Final plane d = PAD (window now at d = PAD).
    float4 r;
    r.x = a.x * b0;
    r.y = a.y * b1;
    r.z = a.z * b2;
    r.w = a.w * b3;
    po[(size_t)PAD * plane_stride_v4] = r;
}

extern "C" void kernel_launch(void* const* d_in, const int* in_sizes, int n_in,
                              void* d_out, int out_size)
{
    const float* in1 = (const float*)d_in[0];
    const float* in2 = (const float*)d_in[1];
    float* out = (float*)d_out;

    corr1d_row_kernel<<<CC * HH, WW / 4>>>(in1, in2, out);
}

// round 14
// speedup vs baseline: 1.0981x; 1.0981x over previous
#include <cuda_runtime.h>
#include <cstddef>

// Problem constants (fixed by the dataset problem)
#define CC 32
#define HH 128
#define WW 512
#define PAD 40
#define DD (PAD + 1)

// out[c,d,h,w] = in1[c,h,w] * (w >= d ? in2[c,h,w-d] : 0)
//
// FINAL (R10 structure, best measured: 53.28us ~= 89% of spec HBM for the
// 378 MB mixed read+write stream — the drain ceiling).
//
// One CTA per (c,h) row (4096 CTAs, 128 threads). in2 row staged once into
// shared memory with a PAD-float zero apron. Thread t owns the aligned float4
// at w = 4t; the shifted in2 window lives in 4 rotating registers.
//
// d-loop unrolled by 2: plane d and d+1 are stored from one window state; the
// window then advances by 2 via two independent SHFL.UPs (prev-lane b2, b3),
// halving the per-plane shuffle dependency chain that gates store issue.
// Only lane 0 touches shared in the loop (conflict-free apron reads).
//
// Stores are evict-first streaming (__stcs) — measured matrix:
//   .cs 53.3us  <<  default 59.5us  ~=  .wt 59.5us.
// Evict-first keeps the 344 MB write-once stream from evicting the read-once
// inputs out of L2 and feeds the writeback scheduler immediately.
__global__ __launch_bounds__(128) void corr1d_row_kernel(
    const float* __restrict__ in1,
    const float* __restrict__ in2,
    float* __restrict__ out)
{
    __shared__ float s2[PAD + WW];   // 552 floats; [0,PAD) is the zero apron

    const int row  = blockIdx.x;     // (c,h) in [0, C*H)
    const int t    = threadIdx.x;    // 0..127
    const int lane = t & 31;
    const int c    = row / HH;
    const int h    = row % HH;

    // Stage rows. PAD*4 = 160 bytes, 16B-aligned, so float4 stores into
    // s2+PAD are legal.
    const float4 a = reinterpret_cast<const float4*>(in1 + (size_t)row * WW)[t];
    if (t < PAD) s2[t] = 0.0f;
    reinterpret_cast<float4*>(s2 + PAD)[t] =
        reinterpret_cast<const float4*>(in2 + (size_t)row * WW)[t];
    __syncthreads();

    // Output base for d=0 plane of this (c,h) row; planes are HH*WW apart.
    float4* po = reinterpret_cast<float4*>(
        out + ((size_t)(c * DD) * HH + h) * WW) + t;
    const size_t plane_stride_v4 = (size_t)HH * WW / 4;   // 16384 float4s

    // d=0 window: one aligned LDS.128.
    float4 b = reinterpret_cast<const float4*>(s2 + PAD)[t];
    float b0 = b.x, b1 = b.y, b2 = b.z, b3 = b.w;

    const int base = PAD + 4 * t;    // s2 index of b0 at d=0

    #pragma unroll
    for (int d = 0; d < PAD; d += 2) {
        // Fetch both carries up front (independent shuffles, issued in
        // parallel; 26-cyc latency covers the two stores below).
        float carry0 = __shfl_up_sync(0xffffffffu, b2, 1);  // W[base-d-2]
        float carry1 = __shfl_up_sync(0xffffffffu, b3, 1);  // W[base-d-1]
        if (lane == 0) {
            carry0 = s2[base - d - 2];   // warp-boundary fill (apron-safe)
            carry1 = s2[base - d - 1];
        }

        // Plane d: window (b0, b1, b2, b3).
        float4 r0;
        r0.x = a.x * b0;
        r0.y = a.y * b1;
        r0.z = a.z * b2;
        r0.w = a.w * b3;
        __stcs(po + (size_t)d * plane_stride_v4, r0);

        // Plane d+1: window (carry1, b0, b1, b2).
        float4 r1;
        r1.x = a.x * carry1;
        r1.y = a.y * b0;
        r1.z = a.z * b1;
        r1.w = a.w * b2;
        __stcs(po + (size_t)(d + 1) * plane_stride_v4, r1);

        // Advance window by 2 disparities.
        b3 = b1;
        b2 = b0;
        b1 = carry1;
        b0 = carry0;
    }

    // Final plane d = PAD (window now at d = PAD).
    float4 r;
    r.x = a.x * b0;
    r.y = a.y * b1;
    r.z = a.z * b2;
    r.w = a.w * b3;
    __stcs(po + (size_t)PAD * plane_stride_v4, r);
}

extern "C" void kernel_launch(void* const* d_in, const int* in_sizes, int n_in,
                              void* d_out, int out_size)
{
    const float* in1 = (const float*)d_in[0];
    const float* in2 = (const float*)d_in[1];
    float* out = (float*)d_out;

    corr1d_row_kernel<<<CC * HH, WW / 4>>>(in1, in2, out);
}